// round 8
// baseline (speedup 1.0000x reference)
#include <cuda_runtime.h>
#include <cuda_fp16.h>
#include <cstdint>
#include <cstddef>

#define MDIM 16384
#define NDIM 4096
#define KDIM 2048
#define HDIM 1024

#define BM 128
#define BN 128
#define BK 64
#define THREADS 256
#define NKT (KDIM / BK)              // 32

#define A_STAGE 16384                // 32 units x 512B (A only)
#define SMEM_ALLOC 67584             // max(4 stages * 16KB, 128*33*16 gate buffer)

// Fragment-packed operands (device globals: allowed scratch)
__device__ __half g_Apack[(size_t)MDIM * KDIM];   // 64 MB
__device__ __half g_Wpack[(size_t)NDIM * KDIM];   // 16 MB

// ---------------- helpers ----------------
__device__ __forceinline__ uint32_t cvta_s(const void* p) {
    return (uint32_t)__cvta_generic_to_shared(p);
}
__device__ __forceinline__ void cp_async16(uint32_t s, const void* g) {
    asm volatile("cp.async.cg.shared.global [%0], [%1], 16;\n" :: "r"(s), "l"(g));
}
__device__ __forceinline__ void cp_commit() { asm volatile("cp.async.commit_group;\n" ::: "memory"); }
#define CP_WAIT(n) asm volatile("cp.async.wait_group %0;\n" :: "n"(n) : "memory")

__device__ __forceinline__ void mma_f16(float* d, const uint32_t* a, const uint32_t* b) {
    asm volatile("mma.sync.aligned.m16n8k16.row.col.f32.f16.f16.f32 "
        "{%0,%1,%2,%3}, {%4,%5,%6,%7}, {%8,%9}, {%0,%1,%2,%3};\n"
        : "+f"(d[0]), "+f"(d[1]), "+f"(d[2]), "+f"(d[3])
        : "r"(a[0]), "r"(a[1]), "r"(a[2]), "r"(a[3]), "r"(b[0]), "r"(b[1]));
}
__device__ __forceinline__ float tanh_fast(float x) {
    float r; asm("tanh.approx.f32 %0, %1;\n" : "=f"(r) : "f"(x)); return r;
}
__device__ __forceinline__ float sigmoid_fast(float x) {
    return fmaf(tanh_fast(0.5f * x), 0.5f, 0.5f);
}

// ---------------- merged pack kernel (verified round 7) ----------------
__global__ void pack_AW(const float* __restrict__ inc, const float* __restrict__ oh,
                        const float* __restrict__ Wi, const float* __restrict__ Wh,
                        int aBlocks) {
    if ((int)blockIdx.x < aBlocks) {
        int idx = blockIdx.x * blockDim.x + threadIdx.x;
        int lane = idx & 31;
        int unit = idx >> 5;
        int kblk = unit & 127;
        int mblk = unit >> 7;
        int gid = lane >> 2, q = lane & 3;
        int m0 = mblk * 16 + gid;
        int k0 = kblk * 16 + 2 * q;
        const float* src;
        if (k0 < 1024) src = inc + (size_t)m0 * 1024 + k0;
        else           src = oh  + (size_t)m0 * 1024 + (k0 - 1024);
        float2 v0 = *(const float2*)(src);
        float2 v1 = *(const float2*)(src + 8 * 1024);
        float2 v2 = *(const float2*)(src + 8);
        float2 v3 = *(const float2*)(src + 8 * 1024 + 8);
        __half2 h[4];
        h[0] = __floats2half2_rn(v0.x, v0.y);
        h[1] = __floats2half2_rn(v1.x, v1.y);
        h[2] = __floats2half2_rn(v2.x, v2.y);
        h[3] = __floats2half2_rn(v3.x, v3.y);
        *(float4*)(g_Apack + (size_t)unit * 256 + lane * 8) = *(float4*)h;
    } else {
        int idx = (blockIdx.x - aBlocks) * blockDim.x + threadIdx.x;
        int lane = idx & 31;
        int unit = idx >> 5;
        int kblk = unit & 63;
        int nblk = unit >> 6;
        int gid = lane >> 2, q = lane & 3;
        int n = nblk * 8 + gid;
        int g = n & 3, hh = n >> 2;
        int k0 = kblk * 32 + 2 * q;
        const float* src;
        if (k0 < 1024) src = Wi + ((size_t)g * 1024 + hh) * 1024 + k0;
        else           src = Wh + ((size_t)g * 1024 + hh) * 1024 + (k0 - 1024);
        float2 v0 = *(const float2*)(src);
        float2 v1 = *(const float2*)(src + 8);
        float2 v2 = *(const float2*)(src + 16);
        float2 v3 = *(const float2*)(src + 24);
        __half2 h[4];
        h[0] = __floats2half2_rn(v0.x, v0.y);
        h[1] = __floats2half2_rn(v1.x, v1.y);
        h[2] = __floats2half2_rn(v2.x, v2.y);
        h[3] = __floats2half2_rn(v3.x, v3.y);
        *(float4*)(g_Wpack + (size_t)unit * 256 + lane * 8) = *(float4*)h;
    }
}

// ---------------- main GEMM + fused LSTM epilogue ----------------
// 8 warps, warp tile 64x32, warp grid 2(M) x 4(N); 2 CTAs/SM.
// A: cp.async -> smem (4 stages). B: __ldg -> registers, single-buffered with
// mid-consume reload (WAR on bfr regs orders LDG after last HMMA read).
__global__ void __launch_bounds__(THREADS, 2)
lstm_mma(const float* __restrict__ old_c, const float* __restrict__ bi,
         float* __restrict__ out, long long out_size)
{
    extern __shared__ char dsm[];
    __shared__ float4 s_bias4[32];

    const int tid  = threadIdx.x;
    const int lane = tid & 31;
    const int warp = tid >> 5;            // 0..7
    const int wr = warp >> 2;             // 0..1 -> M
    const int wc = warp & 3;              // 0..3 -> N
    const int bm = blockIdx.y * BM;
    const int bn = blockIdx.x * BN;
    const int gid = lane >> 2, q = lane & 3;

    const uint32_t smem = cvta_s(dsm);

    if (tid < 32) {
        int hg = (bn >> 2) + tid;
        s_bias4[tid] = make_float4(bi[hg], bi[1024 + hg], bi[2048 + hg], bi[3072 + hg]);
    }

    float acc[4][4][4];
#pragma unroll
    for (int a = 0; a < 4; a++)
#pragma unroll
        for (int b = 0; b < 4; b++)
#pragma unroll
            for (int c = 0; c < 4; c++) acc[a][b][c] = 0.f;

    const size_t a_row_unit = (size_t)(bm / 16) * 128;
    // B unit base for this warp's 4 n-blocks (nblk = wc*4+nt), per ktile offset kt*2+ks32
    const size_t b_unit0 = (size_t)(bn / 8 + wc * 4) * 64;

    uint32_t bfr0[4][4], bfr1[4][4];     // ks32 = 0 / 1 fragments (current ktile)

    auto ldgB = [&](int kt, int ks32, uint32_t (*bfr)[4]) {
#pragma unroll
        for (int nt = 0; nt < 4; nt++) {
            const uint4* p = (const uint4*)(g_Wpack +
                (b_unit0 + (size_t)nt * 64 + kt * 2 + ks32) * 256 + lane * 8);
            uint4 v = __ldg(p);
            bfr[nt][0] = v.x; bfr[nt][1] = v.y; bfr[nt][2] = v.z; bfr[nt][3] = v.w;
        }
    };

    auto produce = [&](int kt, int st) {
        uint32_t sa = smem + st * A_STAGE;
#pragma unroll
        for (int i = 0; i < 4; i++) {
            int u = warp * 4 + i;              // 0..31: mblk = u>>2, ks16 = u&3
            const __half* src = g_Apack +
                (a_row_unit + (size_t)(u >> 2) * 128 + kt * 4 + (u & 3)) * 256 + lane * 8;
            cp_async16(sa + u * 512 + lane * 16, src);
        }
    };

    // consume ktile in stage st; reload bfr with nextkt's fragments mid-stream
    auto consume = [&](int st, int nextkt) {
        const char* sA = dsm + st * A_STAGE;
        // ---- ks32 = 0 (bfr0) ----
#pragma unroll
        for (int ki = 0; ki < 2; ki++) {
            uint32_t afr[4][4];
#pragma unroll
            for (int mt = 0; mt < 4; mt++)
                *(uint4*)afr[mt] = *(const uint4*)(sA + ((wr * 4 + mt) * 4 + ki) * 512 + lane * 16);
#pragma unroll
            for (int mt = 0; mt < 4; mt++)
#pragma unroll
                for (int nt = 0; nt < 4; nt++)
                    mma_f16(acc[mt][nt], afr[mt], &bfr0[nt][ki * 2]);
        }
        ldgB(nextkt, 0, bfr0);               // reload freed regs; hidden by ks32=1 math
        // ---- ks32 = 1 (bfr1) ----
#pragma unroll
        for (int ki = 0; ki < 2; ki++) {
            uint32_t afr[4][4];
#pragma unroll
            for (int mt = 0; mt < 4; mt++)
                *(uint4*)afr[mt] = *(const uint4*)(sA + ((wr * 4 + mt) * 4 + 2 + ki) * 512 + lane * 16);
#pragma unroll
            for (int mt = 0; mt < 4; mt++)
#pragma unroll
                for (int nt = 0; nt < 4; nt++)
                    mma_f16(acc[mt][nt], afr[mt], &bfr1[nt][ki * 2]);
        }
        ldgB(nextkt, 1, bfr1);
    };

    // prologue: A stages 0..2, B ktile 0
    produce(0, 0); cp_commit();
    produce(1, 1); cp_commit();
    produce(2, 2); cp_commit();
    ldgB(0, 0, bfr0);
    ldgB(0, 1, bfr1);

    // unroll-4 mainloop: stage indices compile-time per position
#pragma unroll 1
    for (int kt = 0; kt < NKT; kt += 4) {
        CP_WAIT(2); __syncthreads();
        produce(kt + 3, 3); cp_commit();
        consume(0, (kt + 1 < NKT) ? kt + 1 : NKT - 1);

        CP_WAIT(2); __syncthreads();
        if (kt + 4 < NKT) produce(kt + 4, 0);
        cp_commit();
        consume(1, (kt + 2 < NKT) ? kt + 2 : NKT - 1);

        CP_WAIT(2); __syncthreads();
        if (kt + 5 < NKT) produce(kt + 5, 1);
        cp_commit();
        consume(2, (kt + 3 < NKT) ? kt + 3 : NKT - 1);

        CP_WAIT(2); __syncthreads();
        if (kt + 6 < NKT) produce(kt + 6, 2);
        cp_commit();
        consume(3, (kt + 4 < NKT) ? kt + 4 : NKT - 1);
    }

    CP_WAIT(0);
    __syncthreads();

    // ---- Phase A: dump raw gate pre-activations to smem ----
    float* sg = (float*)dsm;
#pragma unroll
    for (int mt = 0; mt < 4; mt++) {
#pragma unroll
        for (int rr = 0; rr < 2; rr++) {
            int row = wr * 64 + mt * 16 + gid + rr * 8;
#pragma unroll
            for (int nt = 0; nt < 4; nt++) {
                int h = wc * 8 + nt * 2 + (q >> 1);
                *(float2*)(sg + (row * 33 + h) * 4 + (q & 1) * 2) =
                    make_float2(acc[mt][nt][rr * 2 + 0], acc[mt][nt][rr * 2 + 1]);
            }
        }
    }
    __syncthreads();

    // ---- Phase B: coalesced cell update + streaming stores ----
    const long long BH = (long long)MDIM * HDIM;
    const bool seg1 = out_size >= 2 * BH;
    const bool seg2 = out_size >= 3 * BH;
    const int hbase = bn >> 2;

#pragma unroll 4
    for (int it = 0; it < 16; it++) {
        int idx = it * THREADS + tid;
        int row = idx >> 5;
        int h   = idx & 31;
        float4 ga = *(const float4*)(sg + (row * 33 + h) * 4);
        float4 bb = s_bias4[h];
        size_t gidx = (size_t)(bm + row) * HDIM + hbase + h;
        float oc = __ldcs(old_c + gidx);
        float iv = sigmoid_fast(ga.x + bb.x);
        float fv = sigmoid_fast(ga.y + bb.y);
        float gv = tanh_fast(ga.z + bb.z);
        float ov = sigmoid_fast(ga.w + bb.w);
        float nc = fmaf(fv, oc, iv * gv);
        float nh = ov * tanh_fast(nc);
        __stcs(out + gidx, nh);
        if (seg1) __stcs(out + BH + gidx, nh);
        if (seg2) __stcs(out + 2 * BH + gidx, nc);
    }
}

extern "C" void kernel_launch(void* const* d_in, const int* in_sizes, int n_in,
                              void* d_out, int out_size) {
    const float* incoming = (const float*)d_in[0];
    const float* old_h    = (const float*)d_in[1];
    const float* old_c    = (const float*)d_in[2];
    const float* Wi       = (const float*)d_in[3];
    const float* bi       = (const float*)d_in[4];
    const float* Wh       = (const float*)d_in[5];
    float* out = (float*)d_out;

    int aBlocks = (MDIM / 16) * (KDIM / 16) * 32 / 256;   // 16384
    int wBlocks = (NDIM / 8) * (KDIM / 32) * 32 / 256;    // 4096
    pack_AW<<<aBlocks + wBlocks, 256>>>(incoming, old_h, Wi, Wh, aBlocks);

    static int smem_set = 0;
    if (!smem_set) {
        cudaFuncSetAttribute(lstm_mma, cudaFuncAttributeMaxDynamicSharedMemorySize,
                             SMEM_ALLOC);
        smem_set = 1;
    }
    dim3 grid(NDIM / BN, MDIM / BM);   // (32, 128)
    lstm_mma<<<grid, THREADS, SMEM_ALLOC>>>(old_c, bi, out, (long long)out_size);
}

// round 9
// speedup vs baseline: 1.0583x; 1.0583x over previous
#include <cuda_runtime.h>
#include <cuda_fp16.h>
#include <cstdint>
#include <cstddef>

#define MDIM 16384
#define NDIM 4096
#define KDIM 2048
#define HDIM 1024

#define BM 128
#define BN 128
#define BK 64
#define STAGES 3
#define THREADS 256
#define NKT (KDIM / BK)              // 32

#define A_BYTES 16384
#define B_BYTES 16384
#define STAGE_BYTES (A_BYTES + B_BYTES)   // 32768

// Fragment-packed operands (device globals: allowed scratch)
__device__ __half g_Apack[(size_t)MDIM * KDIM];   // 64 MB
__device__ __half g_Wpack[(size_t)NDIM * KDIM];   // 16 MB

// ---------------- helpers ----------------
__device__ __forceinline__ uint32_t cvta_s(const void* p) {
    return (uint32_t)__cvta_generic_to_shared(p);
}
__device__ __forceinline__ void cp_async16(uint32_t s, const void* g) {
    asm volatile("cp.async.cg.shared.global [%0], [%1], 16;\n" :: "r"(s), "l"(g));
}
__device__ __forceinline__ void cp_commit() { asm volatile("cp.async.commit_group;\n" ::: "memory"); }
#define CP_WAIT(n) asm volatile("cp.async.wait_group %0;\n" :: "n"(n) : "memory")

__device__ __forceinline__ void mma_f16(float* d, const uint32_t* a, const uint32_t* b) {
    asm volatile("mma.sync.aligned.m16n8k16.row.col.f32.f16.f16.f32 "
        "{%0,%1,%2,%3}, {%4,%5,%6,%7}, {%8,%9}, {%0,%1,%2,%3};\n"
        : "+f"(d[0]), "+f"(d[1]), "+f"(d[2]), "+f"(d[3])
        : "r"(a[0]), "r"(a[1]), "r"(a[2]), "r"(a[3]), "r"(b[0]), "r"(b[1]));
}
__device__ __forceinline__ float tanh_fast(float x) {
    float r; asm("tanh.approx.f32 %0, %1;\n" : "=f"(r) : "f"(x)); return r;
}
__device__ __forceinline__ float sigmoid_fast(float x) {
    return fmaf(tanh_fast(0.5f * x), 0.5f, 0.5f);
}

// ---------------- merged pack kernel (verified round 7) ----------------
__global__ void pack_AW(const float* __restrict__ inc, const float* __restrict__ oh,
                        const float* __restrict__ Wi, const float* __restrict__ Wh,
                        int aBlocks) {
    if ((int)blockIdx.x < aBlocks) {
        int idx = blockIdx.x * blockDim.x + threadIdx.x;
        int lane = idx & 31;
        int unit = idx >> 5;
        int kblk = unit & 127;
        int mblk = unit >> 7;
        int gid = lane >> 2, q = lane & 3;
        int m0 = mblk * 16 + gid;
        int k0 = kblk * 16 + 2 * q;
        const float* src;
        if (k0 < 1024) src = inc + (size_t)m0 * 1024 + k0;
        else           src = oh  + (size_t)m0 * 1024 + (k0 - 1024);
        float2 v0 = *(const float2*)(src);
        float2 v1 = *(const float2*)(src + 8 * 1024);
        float2 v2 = *(const float2*)(src + 8);
        float2 v3 = *(const float2*)(src + 8 * 1024 + 8);
        __half2 h[4];
        h[0] = __floats2half2_rn(v0.x, v0.y);
        h[1] = __floats2half2_rn(v1.x, v1.y);
        h[2] = __floats2half2_rn(v2.x, v2.y);
        h[3] = __floats2half2_rn(v3.x, v3.y);
        *(float4*)(g_Apack + (size_t)unit * 256 + lane * 8) = *(float4*)h;
    } else {
        int idx = (blockIdx.x - aBlocks) * blockDim.x + threadIdx.x;
        int lane = idx & 31;
        int unit = idx >> 5;
        int kblk = unit & 63;
        int nblk = unit >> 6;
        int gid = lane >> 2, q = lane & 3;
        int n = nblk * 8 + gid;
        int g = n & 3, hh = n >> 2;
        int k0 = kblk * 32 + 2 * q;
        const float* src;
        if (k0 < 1024) src = Wi + ((size_t)g * 1024 + hh) * 1024 + k0;
        else           src = Wh + ((size_t)g * 1024 + hh) * 1024 + (k0 - 1024);
        float2 v0 = *(const float2*)(src);
        float2 v1 = *(const float2*)(src + 8);
        float2 v2 = *(const float2*)(src + 16);
        float2 v3 = *(const float2*)(src + 24);
        __half2 h[4];
        h[0] = __floats2half2_rn(v0.x, v0.y);
        h[1] = __floats2half2_rn(v1.x, v1.y);
        h[2] = __floats2half2_rn(v2.x, v2.y);
        h[3] = __floats2half2_rn(v3.x, v3.y);
        *(float4*)(g_Wpack + (size_t)unit * 256 + lane * 8) = *(float4*)h;
    }
}

// ---------------- main GEMM + fused LSTM epilogue ----------------
// 8 warps, warp tile 64x32, warp grid 2(M) x 4(N); 2 CTAs/SM.
__global__ void __launch_bounds__(THREADS, 2)
lstm_mma(const float* __restrict__ old_c, const float* __restrict__ bi,
         float* __restrict__ out, long long out_size)
{
    extern __shared__ char dsm[];
    __shared__ float4 s_bias4[32];

    const int tid  = threadIdx.x;
    const int lane = tid & 31;
    const int warp = tid >> 5;            // 0..7
    const int wr = warp >> 2;             // 0..1 -> M
    const int wc = warp & 3;              // 0..3 -> N
    const int bm = blockIdx.y * BM;
    const int bn = blockIdx.x * BN;
    const int gid = lane >> 2, q = lane & 3;

    const uint32_t smem = cvta_s(dsm);

    if (tid < 32) {
        int hg = (bn >> 2) + tid;
        s_bias4[tid] = make_float4(bi[hg], bi[1024 + hg], bi[2048 + hg], bi[3072 + hg]);
    }

    float acc[4][4][4];
#pragma unroll
    for (int a = 0; a < 4; a++)
#pragma unroll
        for (int b = 0; b < 4; b++)
#pragma unroll
            for (int c = 0; c < 4; c++) acc[a][b][c] = 0.f;

    const size_t a_row_unit = (size_t)(bm / 16) * 128;
    const size_t b_row_unit = (size_t)(bn / 8) * 64;

    auto produce = [&](int kt, int st) {
        uint32_t sa = smem + st * STAGE_BYTES;
        uint32_t sb = sa + A_BYTES;
#pragma unroll
        for (int i = 0; i < 4; i++) {
            int u = warp * 4 + i;
            const __half* src = g_Apack +
                (a_row_unit + (size_t)(u >> 2) * 128 + kt * 4 + (u & 3)) * 256 + lane * 8;
            cp_async16(sa + u * 512 + lane * 16, src);
        }
#pragma unroll
        for (int i = 0; i < 4; i++) {
            int u = warp * 4 + i;
            const __half* src = g_Wpack +
                (b_row_unit + (size_t)(u >> 1) * 64 + kt * 2 + (u & 1)) * 256 + lane * 8;
            cp_async16(sb + u * 512 + lane * 16, src);
        }
    };

    // software-pipelined consume: LDS for the next k-step issues between HMMA groups
    auto consume = [&](int st) {
        const char* sA = dsm + st * STAGE_BYTES;
        const char* sB = sA + A_BYTES;
        uint32_t afr[2][4][4];
        uint32_t bfr[4][4];
        // prime: afr slot0 <- ks16=0, bfr <- ks32=0
#pragma unroll
        for (int mt = 0; mt < 4; mt++)
            *(uint4*)afr[0][mt] = *(const uint4*)(sA + ((wr * 4 + mt) * 4 + 0) * 512 + lane * 16);
#pragma unroll
        for (int nt = 0; nt < 4; nt++)
            *(uint4*)bfr[nt] = *(const uint4*)(sB + ((wc * 4 + nt) * 2 + 0) * 512 + lane * 16);
        // ks16=0: prefetch afr slot1 <- ks16=1
#pragma unroll
        for (int mt = 0; mt < 4; mt++)
            *(uint4*)afr[1][mt] = *(const uint4*)(sA + ((wr * 4 + mt) * 4 + 1) * 512 + lane * 16);
#pragma unroll
        for (int mt = 0; mt < 4; mt++)
#pragma unroll
            for (int nt = 0; nt < 4; nt++)
                mma_f16(acc[mt][nt], afr[0][mt], &bfr[nt][0]);
        // ks16=1: prefetch afr slot0 <- ks16=2
#pragma unroll
        for (int mt = 0; mt < 4; mt++)
            *(uint4*)afr[0][mt] = *(const uint4*)(sA + ((wr * 4 + mt) * 4 + 2) * 512 + lane * 16);
#pragma unroll
        for (int mt = 0; mt < 4; mt++)
#pragma unroll
            for (int nt = 0; nt < 4; nt++)
                mma_f16(acc[mt][nt], afr[1][mt], &bfr[nt][2]);
        // reload bfr <- ks32=1 (WAR safe: prior HMMAs already issued)
#pragma unroll
        for (int nt = 0; nt < 4; nt++)
            *(uint4*)bfr[nt] = *(const uint4*)(sB + ((wc * 4 + nt) * 2 + 1) * 512 + lane * 16);
        // ks16=2: prefetch afr slot1 <- ks16=3
#pragma unroll
        for (int mt = 0; mt < 4; mt++)
            *(uint4*)afr[1][mt] = *(const uint4*)(sA + ((wr * 4 + mt) * 4 + 3) * 512 + lane * 16);
#pragma unroll
        for (int mt = 0; mt < 4; mt++)
#pragma unroll
            for (int nt = 0; nt < 4; nt++)
                mma_f16(acc[mt][nt], afr[0][mt], &bfr[nt][0]);
        // ks16=3
#pragma unroll
        for (int mt = 0; mt < 4; mt++)
#pragma unroll
            for (int nt = 0; nt < 4; nt++)
                mma_f16(acc[mt][nt], afr[1][mt], &bfr[nt][2]);
    };

    // prologue: stages 0,1
    produce(0, 0); cp_commit();
    produce(1, 1); cp_commit();

    // unroll-3 mainloop: stage indices compile-time constants per position
#pragma unroll 1
    for (int kt = 0; kt < 30; kt += 3) {
        CP_WAIT(1); __syncthreads();
        produce(kt + 2, 2); cp_commit();
        consume(0);

        CP_WAIT(1); __syncthreads();
        produce(kt + 3, 0); cp_commit();
        consume(1);

        CP_WAIT(1); __syncthreads();
        if (kt + 4 < NKT) produce(kt + 4, 1);
        cp_commit();
        consume(2);
    }
    // tail: kt = 30 (stage 0), kt = 31 (stage 1)
    CP_WAIT(1); __syncthreads();
    cp_commit();
    consume(0);
    CP_WAIT(0); __syncthreads();
    consume(1);

    // ---- prefetch old_c (coalesced, streaming) while Phase A runs ----
    const int hbase = bn >> 2;
    float ocs[16];
#pragma unroll
    for (int it = 0; it < 16; it++) {
        int idx = it * THREADS + tid;
        int row = idx >> 5;
        int h   = idx & 31;
        ocs[it] = __ldcs(old_c + (size_t)(bm + row) * HDIM + hbase + h);
    }

    __syncthreads();

    // ---- Phase A: dump raw gate pre-activations to smem ----
    float* sg = (float*)dsm;
#pragma unroll
    for (int mt = 0; mt < 4; mt++) {
#pragma unroll
        for (int rr = 0; rr < 2; rr++) {
            int row = wr * 64 + mt * 16 + gid + rr * 8;
#pragma unroll
            for (int nt = 0; nt < 4; nt++) {
                int h = wc * 8 + nt * 2 + (q >> 1);
                *(float2*)(sg + (row * 33 + h) * 4 + (q & 1) * 2) =
                    make_float2(acc[mt][nt][rr * 2 + 0], acc[mt][nt][rr * 2 + 1]);
            }
        }
    }
    __syncthreads();

    // ---- Phase B: coalesced cell update + streaming stores ----
    const long long BH = (long long)MDIM * HDIM;
    const bool seg1 = out_size >= 2 * BH;
    const bool seg2 = out_size >= 3 * BH;

#pragma unroll 4
    for (int it = 0; it < 16; it++) {
        int idx = it * THREADS + tid;
        int row = idx >> 5;
        int h   = idx & 31;
        float4 ga = *(const float4*)(sg + (row * 33 + h) * 4);
        float4 bb = s_bias4[h];
        size_t gidx = (size_t)(bm + row) * HDIM + hbase + h;
        float iv = sigmoid_fast(ga.x + bb.x);
        float fv = sigmoid_fast(ga.y + bb.y);
        float gv = tanh_fast(ga.z + bb.z);
        float ov = sigmoid_fast(ga.w + bb.w);
        float nc = fmaf(fv, ocs[it], iv * gv);
        float nh = ov * tanh_fast(nc);
        __stcs(out + gidx, nh);
        if (seg1) __stcs(out + BH + gidx, nh);
        if (seg2) __stcs(out + 2 * BH + gidx, nc);
    }
}

extern "C" void kernel_launch(void* const* d_in, const int* in_sizes, int n_in,
                              void* d_out, int out_size) {
    const float* incoming = (const float*)d_in[0];
    const float* old_h    = (const float*)d_in[1];
    const float* old_c    = (const float*)d_in[2];
    const float* Wi       = (const float*)d_in[3];
    const float* bi       = (const float*)d_in[4];
    const float* Wh       = (const float*)d_in[5];
    float* out = (float*)d_out;

    int aBlocks = (MDIM / 16) * (KDIM / 16) * 32 / 256;   // 16384
    int wBlocks = (NDIM / 8) * (KDIM / 32) * 32 / 256;    // 4096
    pack_AW<<<aBlocks + wBlocks, 256>>>(incoming, old_h, Wi, Wh, aBlocks);

    static int smem_set = 0;
    if (!smem_set) {
        cudaFuncSetAttribute(lstm_mma, cudaFuncAttributeMaxDynamicSharedMemorySize,
                             STAGES * STAGE_BYTES);
        smem_set = 1;
    }
    dim3 grid(NDIM / BN, MDIM / BM);   // (32, 128)
    lstm_mma<<<grid, THREADS, STAGES * STAGE_BYTES>>>(old_c, bi, out, (long long)out_size);
}

// round 11
// speedup vs baseline: 1.0642x; 1.0056x over previous
#include <cuda_runtime.h>
#include <cuda_fp16.h>
#include <cstdint>
#include <cstddef>

#define MDIM 16384
#define NDIM 4096
#define KDIM 2048
#define HDIM 1024

#define BM 128
#define BN 128
#define BK 64
#define STAGES 3
#define THREADS 256
#define NKT (KDIM / BK)              // 32

#define A_BYTES 16384
#define B_BYTES 16384
#define STAGE_BYTES (A_BYTES + B_BYTES)   // 32768

// Fragment-packed operands (device globals: allowed scratch)
__device__ __half g_Apack[(size_t)MDIM * KDIM];   // 64 MB
__device__ __half g_Wpack[(size_t)NDIM * KDIM];   // 16 MB

// ---------------- helpers ----------------
__device__ __forceinline__ uint32_t cvta_s(const void* p) {
    return (uint32_t)__cvta_generic_to_shared(p);
}
__device__ __forceinline__ void cp_async16(uint32_t s, const void* g) {
    asm volatile("cp.async.cg.shared.global [%0], [%1], 16;\n" :: "r"(s), "l"(g));
}
__device__ __forceinline__ void cp_commit() { asm volatile("cp.async.commit_group;\n" ::: "memory"); }
#define CP_WAIT(n) asm volatile("cp.async.wait_group %0;\n" :: "n"(n) : "memory")

__device__ __forceinline__ void mma_f16(float* d, const uint32_t* a, const uint32_t* b) {
    asm volatile("mma.sync.aligned.m16n8k16.row.col.f32.f16.f16.f32 "
        "{%0,%1,%2,%3}, {%4,%5,%6,%7}, {%8,%9}, {%0,%1,%2,%3};\n"
        : "+f"(d[0]), "+f"(d[1]), "+f"(d[2]), "+f"(d[3])
        : "r"(a[0]), "r"(a[1]), "r"(a[2]), "r"(a[3]), "r"(b[0]), "r"(b[1]));
}
__device__ __forceinline__ float tanh_fast(float x) {
    float r; asm("tanh.approx.f32 %0, %1;\n" : "=f"(r) : "f"(x)); return r;
}
__device__ __forceinline__ float sigmoid_fast(float x) {
    return fmaf(tanh_fast(0.5f * x), 0.5f, 0.5f);
}

// ---------------- merged pack kernel (verified round 7) ----------------
__global__ void pack_AW(const float* __restrict__ inc, const float* __restrict__ oh,
                        const float* __restrict__ Wi, const float* __restrict__ Wh,
                        int aBlocks) {
    if ((int)blockIdx.x < aBlocks) {
        int idx = blockIdx.x * blockDim.x + threadIdx.x;
        int lane = idx & 31;
        int unit = idx >> 5;
        int kblk = unit & 127;
        int mblk = unit >> 7;
        int gid = lane >> 2, q = lane & 3;
        int m0 = mblk * 16 + gid;
        int k0 = kblk * 16 + 2 * q;
        const float* src;
        if (k0 < 1024) src = inc + (size_t)m0 * 1024 + k0;
        else           src = oh  + (size_t)m0 * 1024 + (k0 - 1024);
        float2 v0 = *(const float2*)(src);
        float2 v1 = *(const float2*)(src + 8 * 1024);
        float2 v2 = *(const float2*)(src + 8);
        float2 v3 = *(const float2*)(src + 8 * 1024 + 8);
        __half2 h[4];
        h[0] = __floats2half2_rn(v0.x, v0.y);
        h[1] = __floats2half2_rn(v1.x, v1.y);
        h[2] = __floats2half2_rn(v2.x, v2.y);
        h[3] = __floats2half2_rn(v3.x, v3.y);
        *(float4*)(g_Apack + (size_t)unit * 256 + lane * 8) = *(float4*)h;
    } else {
        int idx = (blockIdx.x - aBlocks) * blockDim.x + threadIdx.x;
        int lane = idx & 31;
        int unit = idx >> 5;
        int kblk = unit & 63;
        int nblk = unit >> 6;
        int gid = lane >> 2, q = lane & 3;
        int n = nblk * 8 + gid;
        int g = n & 3, hh = n >> 2;
        int k0 = kblk * 32 + 2 * q;
        const float* src;
        if (k0 < 1024) src = Wi + ((size_t)g * 1024 + hh) * 1024 + k0;
        else           src = Wh + ((size_t)g * 1024 + hh) * 1024 + (k0 - 1024);
        float2 v0 = *(const float2*)(src);
        float2 v1 = *(const float2*)(src + 8);
        float2 v2 = *(const float2*)(src + 16);
        float2 v3 = *(const float2*)(src + 24);
        __half2 h[4];
        h[0] = __floats2half2_rn(v0.x, v0.y);
        h[1] = __floats2half2_rn(v1.x, v1.y);
        h[2] = __floats2half2_rn(v2.x, v2.y);
        h[3] = __floats2half2_rn(v3.x, v3.y);
        *(float4*)(g_Wpack + (size_t)unit * 256 + lane * 8) = *(float4*)h;
    }
}

// ---------------- main GEMM + fused LSTM epilogue ----------------
// 8 warps, warp tile 64x32, warp grid 2(M) x 4(N); 2 CTAs/SM.
__global__ void __launch_bounds__(THREADS, 2)
lstm_mma(const float* __restrict__ old_c, const float* __restrict__ bi,
         float* __restrict__ out, long long out_size)
{
    extern __shared__ char dsm[];
    __shared__ float4 s_bias4[32];

    const int tid  = threadIdx.x;
    const int lane = tid & 31;
    const int warp = tid >> 5;            // 0..7
    const int wr = warp >> 2;             // 0..1 -> M
    const int wc = warp & 3;              // 0..3 -> N
    const int bm = blockIdx.y * BM;
    const int bn = blockIdx.x * BN;
    const int gid = lane >> 2, q = lane & 3;

    const uint32_t smem = cvta_s(dsm);

    if (tid < 32) {
        int hg = (bn >> 2) + tid;
        s_bias4[tid] = make_float4(bi[hg], bi[1024 + hg], bi[2048 + hg], bi[3072 + hg]);
    }

    float acc[4][4][4];
#pragma unroll
    for (int a = 0; a < 4; a++)
#pragma unroll
        for (int b = 0; b < 4; b++)
#pragma unroll
            for (int c = 0; c < 4; c++) acc[a][b][c] = 0.f;

    const size_t a_row_unit = (size_t)(bm / 16) * 128;
    const size_t b_row_unit = (size_t)(bn / 8) * 64;

    auto produceA = [&](int kt, int st) {
        uint32_t sa = smem + st * STAGE_BYTES;
#pragma unroll
        for (int i = 0; i < 4; i++) {
            int u = warp * 4 + i;
            const __half* src = g_Apack +
                (a_row_unit + (size_t)(u >> 2) * 128 + kt * 4 + (u & 3)) * 256 + lane * 8;
            cp_async16(sa + u * 512 + lane * 16, src);
        }
    };
    auto produceB = [&](int kt, int st) {
        uint32_t sb = smem + st * STAGE_BYTES + A_BYTES;
#pragma unroll
        for (int i = 0; i < 4; i++) {
            int u = warp * 4 + i;
            const __half* src = g_Wpack +
                (b_row_unit + (size_t)(u >> 1) * 64 + kt * 2 + (u & 1)) * 256 + lane * 8;
            cp_async16(sb + u * 512 + lane * 16, src);
        }
    };

    // consume ktile in stage st; optionally interleave production of ktile nk
    // into stage pst between HMMA groups (doProd=false for the tail).
    auto consume = [&](int st, bool doProd, int nk, int pst) {
        const char* sA = dsm + st * STAGE_BYTES;
        const char* sB = sA + A_BYTES;
        uint32_t afr[2][4][4];
        uint32_t bfr[4][4];
        // prime: afr slot0 <- ks16=0, bfr <- ks32=0
#pragma unroll
        for (int mt = 0; mt < 4; mt++)
            *(uint4*)afr[0][mt] = *(const uint4*)(sA + ((wr * 4 + mt) * 4 + 0) * 512 + lane * 16);
#pragma unroll
        for (int nt = 0; nt < 4; nt++)
            *(uint4*)bfr[nt] = *(const uint4*)(sB + ((wc * 4 + nt) * 2 + 0) * 512 + lane * 16);
        // prefetch afr slot1 <- ks16=1
#pragma unroll
        for (int mt = 0; mt < 4; mt++)
            *(uint4*)afr[1][mt] = *(const uint4*)(sA + ((wr * 4 + mt) * 4 + 1) * 512 + lane * 16);
        // ks16=0
#pragma unroll
        for (int mt = 0; mt < 4; mt++)
#pragma unroll
            for (int nt = 0; nt < 4; nt++)
                mma_f16(acc[mt][nt], afr[0][mt], &bfr[nt][0]);
        if (doProd) produceA(nk, pst);            // A copies overlap ks16=1 math
        // prefetch afr slot0 <- ks16=2
#pragma unroll
        for (int mt = 0; mt < 4; mt++)
            *(uint4*)afr[0][mt] = *(const uint4*)(sA + ((wr * 4 + mt) * 4 + 2) * 512 + lane * 16);
        // ks16=1
#pragma unroll
        for (int mt = 0; mt < 4; mt++)
#pragma unroll
            for (int nt = 0; nt < 4; nt++)
                mma_f16(acc[mt][nt], afr[1][mt], &bfr[nt][2]);
        if (doProd) produceB(nk, pst);            // B copies overlap ks16=2 math
        // reload bfr <- ks32=1 (WAR safe: prior HMMAs already issued)
#pragma unroll
        for (int nt = 0; nt < 4; nt++)
            *(uint4*)bfr[nt] = *(const uint4*)(sB + ((wc * 4 + nt) * 2 + 1) * 512 + lane * 16);
        // prefetch afr slot1 <- ks16=3
#pragma unroll
        for (int mt = 0; mt < 4; mt++)
            *(uint4*)afr[1][mt] = *(const uint4*)(sA + ((wr * 4 + mt) * 4 + 3) * 512 + lane * 16);
        // ks16=2
#pragma unroll
        for (int mt = 0; mt < 4; mt++)
#pragma unroll
            for (int nt = 0; nt < 4; nt++)
                mma_f16(acc[mt][nt], afr[0][mt], &bfr[nt][0]);
        cp_commit();                               // one commit per ktile position
        // ks16=3
#pragma unroll
        for (int mt = 0; mt < 4; mt++)
#pragma unroll
            for (int nt = 0; nt < 4; nt++)
                mma_f16(acc[mt][nt], afr[1][mt], &bfr[nt][2]);
    };

    // prologue: stages 0,1
    produceA(0, 0); produceB(0, 0); cp_commit();
    produceA(1, 1); produceB(1, 1); cp_commit();

    // unroll-3 mainloop, round-9-proven ordering: wait -> barrier -> consume(+produce)
#pragma unroll 1
    for (int kt = 0; kt < 30; kt += 3) {
        CP_WAIT(1); __syncthreads();
        consume(0, true, kt + 2, 2);

        CP_WAIT(1); __syncthreads();
        consume(1, true, kt + 3, 0);

        CP_WAIT(1); __syncthreads();
        consume(2, true, kt + 4, 1);
    }
    // tail: kt=30 (stage 0), kt=31 (stage 1); nothing left to produce.
    // pending after loop: g30, g31
    CP_WAIT(1); __syncthreads();
    consume(0, false, 0, 0);          // kt=30 (commits an empty group; harmless)
    CP_WAIT(0); __syncthreads();
    consume(1, false, 0, 0);          // kt=31

    // ---- prefetch old_c (coalesced, streaming) while Phase A runs ----
    const int hbase = bn >> 2;
    float ocs[16];
#pragma unroll
    for (int it = 0; it < 16; it++) {
        int idx = it * THREADS + tid;
        int row = idx >> 5;
        int h   = idx & 31;
        ocs[it] = __ldcs(old_c + (size_t)(bm + row) * HDIM + hbase + h);
    }

    __syncthreads();

    // ---- Phase A: dump raw gate pre-activations to smem ----
    float* sg = (float*)dsm;
#pragma unroll
    for (int mt = 0; mt < 4; mt++) {
#pragma unroll
        for (int rr = 0; rr < 2; rr++) {
            int row = wr * 64 + mt * 16 + gid + rr * 8;
#pragma unroll
            for (int nt = 0; nt < 4; nt++) {
                int h = wc * 8 + nt * 2 + (q >> 1);
                *(float2*)(sg + (row * 33 + h) * 4 + (q & 1) * 2) =
                    make_float2(acc[mt][nt][rr * 2 + 0], acc[mt][nt][rr * 2 + 1]);
            }
        }
    }
    __syncthreads();

    // ---- Phase B: coalesced cell update + streaming stores ----
    const long long BH = (long long)MDIM * HDIM;
    const bool seg1 = out_size >= 2 * BH;
    const bool seg2 = out_size >= 3 * BH;

#pragma unroll 4
    for (int it = 0; it < 16; it++) {
        int idx = it * THREADS + tid;
        int row = idx >> 5;
        int h   = idx & 31;
        float4 ga = *(const float4*)(sg + (row * 33 + h) * 4);
        float4 bb = s_bias4[h];
        size_t gidx = (size_t)(bm + row) * HDIM + hbase + h;
        float iv = sigmoid_fast(ga.x + bb.x);
        float fv = sigmoid_fast(ga.y + bb.y);
        float gv = tanh_fast(ga.z + bb.z);
        float ov = sigmoid_fast(ga.w + bb.w);
        float nc = fmaf(fv, ocs[it], iv * gv);
        float nh = ov * tanh_fast(nc);
        __stcs(out + gidx, nh);
        if (seg1) __stcs(out + BH + gidx, nh);
        if (seg2) __stcs(out + 2 * BH + gidx, nc);
    }
}

extern "C" void kernel_launch(void* const* d_in, const int* in_sizes, int n_in,
                              void* d_out, int out_size) {
    const float* incoming = (const float*)d_in[0];
    const float* old_h    = (const float*)d_in[1];
    const float* old_c    = (const float*)d_in[2];
    const float* Wi       = (const float*)d_in[3];
    const float* bi       = (const float*)d_in[4];
    const float* Wh       = (const float*)d_in[5];
    float* out = (float*)d_out;

    int aBlocks = (MDIM / 16) * (KDIM / 16) * 32 / 256;   // 16384
    int wBlocks = (NDIM / 8) * (KDIM / 32) * 32 / 256;    // 4096
    pack_AW<<<aBlocks + wBlocks, 256>>>(incoming, old_h, Wi, Wh, aBlocks);

    static int smem_set = 0;
    if (!smem_set) {
        cudaFuncSetAttribute(lstm_mma, cudaFuncAttributeMaxDynamicSharedMemorySize,
                             STAGES * STAGE_BYTES);
        smem_set = 1;
    }
    dim3 grid(NDIM / BN, MDIM / BM);   // (32, 128)
    lstm_mma<<<grid, THREADS, STAGES * STAGE_BYTES>>>(old_c, bi, out, (long long)out_size);
}

// round 12
// speedup vs baseline: 1.0847x; 1.0192x over previous
#include <cuda_runtime.h>
#include <cuda_fp16.h>
#include <cstdint>
#include <cstddef>

#define MDIM 16384
#define NDIM 4096
#define KDIM 2048
#define HDIM 1024

#define BM 128
#define BN 128
#define BK 64
#define STAGES 3
#define THREADS 128
#define NKT (KDIM / BK)              // 32

#define A_BYTES 16384
#define B_BYTES 16384
#define STAGE_BYTES (A_BYTES + B_BYTES)   // 32768

// Fragment-packed operands (device globals: allowed scratch)
__device__ __half g_Apack[(size_t)MDIM * KDIM];   // 64 MB
__device__ __half g_Wpack[(size_t)NDIM * KDIM];   // 16 MB

// ---------------- helpers ----------------
__device__ __forceinline__ uint32_t cvta_s(const void* p) {
    return (uint32_t)__cvta_generic_to_shared(p);
}
__device__ __forceinline__ void cp_async16(uint32_t s, const void* g) {
    asm volatile("cp.async.cg.shared.global [%0], [%1], 16;\n" :: "r"(s), "l"(g));
}
__device__ __forceinline__ void cp_commit() { asm volatile("cp.async.commit_group;\n" ::: "memory"); }
#define CP_WAIT(n) asm volatile("cp.async.wait_group %0;\n" :: "n"(n) : "memory")

__device__ __forceinline__ void mma_f16(float* d, const uint32_t* a, const uint32_t* b) {
    asm volatile("mma.sync.aligned.m16n8k16.row.col.f32.f16.f16.f32 "
        "{%0,%1,%2,%3}, {%4,%5,%6,%7}, {%8,%9}, {%0,%1,%2,%3};\n"
        : "+f"(d[0]), "+f"(d[1]), "+f"(d[2]), "+f"(d[3])
        : "r"(a[0]), "r"(a[1]), "r"(a[2]), "r"(a[3]), "r"(b[0]), "r"(b[1]));
}
__device__ __forceinline__ float tanh_fast(float x) {
    float r; asm("tanh.approx.f32 %0, %1;\n" : "=f"(r) : "f"(x)); return r;
}
__device__ __forceinline__ float sigmoid_fast(float x) {
    return fmaf(tanh_fast(0.5f * x), 0.5f, 0.5f);
}

// ---------------- merged pack kernel (verified round 7) ----------------
__global__ void pack_AW(const float* __restrict__ inc, const float* __restrict__ oh,
                        const float* __restrict__ Wi, const float* __restrict__ Wh,
                        int aBlocks) {
    if ((int)blockIdx.x < aBlocks) {
        int idx = blockIdx.x * blockDim.x + threadIdx.x;
        int lane = idx & 31;
        int unit = idx >> 5;
        int kblk = unit & 127;
        int mblk = unit >> 7;
        int gid = lane >> 2, q = lane & 3;
        int m0 = mblk * 16 + gid;
        int k0 = kblk * 16 + 2 * q;
        const float* src;
        if (k0 < 1024) src = inc + (size_t)m0 * 1024 + k0;
        else           src = oh  + (size_t)m0 * 1024 + (k0 - 1024);
        float2 v0 = *(const float2*)(src);
        float2 v1 = *(const float2*)(src + 8 * 1024);
        float2 v2 = *(const float2*)(src + 8);
        float2 v3 = *(const float2*)(src + 8 * 1024 + 8);
        __half2 h[4];
        h[0] = __floats2half2_rn(v0.x, v0.y);
        h[1] = __floats2half2_rn(v1.x, v1.y);
        h[2] = __floats2half2_rn(v2.x, v2.y);
        h[3] = __floats2half2_rn(v3.x, v3.y);
        *(float4*)(g_Apack + (size_t)unit * 256 + lane * 8) = *(float4*)h;
    } else {
        int idx = (blockIdx.x - aBlocks) * blockDim.x + threadIdx.x;
        int lane = idx & 31;
        int unit = idx >> 5;
        int kblk = unit & 63;
        int nblk = unit >> 6;
        int gid = lane >> 2, q = lane & 3;
        int n = nblk * 8 + gid;
        int g = n & 3, hh = n >> 2;
        int k0 = kblk * 32 + 2 * q;
        const float* src;
        if (k0 < 1024) src = Wi + ((size_t)g * 1024 + hh) * 1024 + k0;
        else           src = Wh + ((size_t)g * 1024 + hh) * 1024 + (k0 - 1024);
        float2 v0 = *(const float2*)(src);
        float2 v1 = *(const float2*)(src + 8);
        float2 v2 = *(const float2*)(src + 16);
        float2 v3 = *(const float2*)(src + 24);
        __half2 h[4];
        h[0] = __floats2half2_rn(v0.x, v0.y);
        h[1] = __floats2half2_rn(v1.x, v1.y);
        h[2] = __floats2half2_rn(v2.x, v2.y);
        h[3] = __floats2half2_rn(v3.x, v3.y);
        *(float4*)(g_Wpack + (size_t)unit * 256 + lane * 8) = *(float4*)h;
    }
}

// ---------------- main GEMM + fused LSTM epilogue ----------------
// 4 warps, warp tile 64x64, warp grid 2(M) x 2(N); 2 CTAs/SM.
__global__ void __launch_bounds__(THREADS, 2)
lstm_mma(const float* __restrict__ old_c, const float* __restrict__ bi,
         float* __restrict__ out, long long out_size)
{
    extern __shared__ char dsm[];
    __shared__ float4 s_bias4[32];

    const int tid  = threadIdx.x;
    const int lane = tid & 31;
    const int warp = tid >> 5;            // 0..3
    const int wr = warp >> 1;             // 0..1 -> M (64 rows each)
    const int wc = warp & 1;              // 0..1 -> N (64 cols each)
    const int bm = blockIdx.y * BM;
    const int bn = blockIdx.x * BN;
    const int gid = lane >> 2, q = lane & 3;

    const uint32_t smem = cvta_s(dsm);

    if (tid < 32) {
        int hg = (bn >> 2) + tid;
        s_bias4[tid] = make_float4(bi[hg], bi[1024 + hg], bi[2048 + hg], bi[3072 + hg]);
    }

    float acc[4][8][4];
#pragma unroll
    for (int a = 0; a < 4; a++)
#pragma unroll
        for (int b = 0; b < 8; b++)
#pragma unroll
            for (int c = 0; c < 4; c++) acc[a][b][c] = 0.f;

    const size_t a_row_unit = (size_t)(bm / 16) * 128;
    const size_t b_row_unit = (size_t)(bn / 8) * 64;

    // per warp: 8 A units + 8 B units per ktile (1 cp.async16/lane each)
    auto produceA = [&](int kt, int st) {
        uint32_t sa = smem + st * STAGE_BYTES;
#pragma unroll
        for (int i = 0; i < 8; i++) {
            int u = warp * 8 + i;              // 0..31: mblk = u>>2, ks16 = u&3
            const __half* src = g_Apack +
                (a_row_unit + (size_t)(u >> 2) * 128 + kt * 4 + (u & 3)) * 256 + lane * 8;
            cp_async16(sa + u * 512 + lane * 16, src);
        }
    };
    auto produceB = [&](int kt, int st) {
        uint32_t sb = smem + st * STAGE_BYTES + A_BYTES;
#pragma unroll
        for (int i = 0; i < 8; i++) {
            int u = warp * 8 + i;              // 0..31: nblk = u>>1, ks32 = u&1
            const __half* src = g_Wpack +
                (b_row_unit + (size_t)(u >> 1) * 64 + kt * 2 + (u & 1)) * 256 + lane * 8;
            cp_async16(sb + u * 512 + lane * 16, src);
        }
    };

    // software-pipelined consume; optionally interleave production of ktile nk
    auto consume = [&](int st, bool doProd, int nk, int pst) {
        const char* sA = dsm + st * STAGE_BYTES;
        const char* sB = sA + A_BYTES;
        uint32_t afr[2][4][4];
        uint32_t bfr[8][4];
        // prime: afr slot0 <- ks16=0, bfr <- ks32=0
#pragma unroll
        for (int mt = 0; mt < 4; mt++)
            *(uint4*)afr[0][mt] = *(const uint4*)(sA + ((wr * 4 + mt) * 4 + 0) * 512 + lane * 16);
#pragma unroll
        for (int nt = 0; nt < 8; nt++)
            *(uint4*)bfr[nt] = *(const uint4*)(sB + ((wc * 8 + nt) * 2 + 0) * 512 + lane * 16);
        // prefetch afr slot1 <- ks16=1
#pragma unroll
        for (int mt = 0; mt < 4; mt++)
            *(uint4*)afr[1][mt] = *(const uint4*)(sA + ((wr * 4 + mt) * 4 + 1) * 512 + lane * 16);
        // ks16=0
#pragma unroll
        for (int mt = 0; mt < 4; mt++)
#pragma unroll
            for (int nt = 0; nt < 8; nt++)
                mma_f16(acc[mt][nt], afr[0][mt], &bfr[nt][0]);
        if (doProd) produceA(nk, pst);            // A copies overlap ks16=1 math
        // prefetch afr slot0 <- ks16=2
#pragma unroll
        for (int mt = 0; mt < 4; mt++)
            *(uint4*)afr[0][mt] = *(const uint4*)(sA + ((wr * 4 + mt) * 4 + 2) * 512 + lane * 16);
        // ks16=1
#pragma unroll
        for (int mt = 0; mt < 4; mt++)
#pragma unroll
            for (int nt = 0; nt < 8; nt++)
                mma_f16(acc[mt][nt], afr[1][mt], &bfr[nt][2]);
        if (doProd) produceB(nk, pst);            // B copies overlap ks16=2 math
        // reload bfr <- ks32=1 (WAR safe: prior HMMAs already issued)
#pragma unroll
        for (int nt = 0; nt < 8; nt++)
            *(uint4*)bfr[nt] = *(const uint4*)(sB + ((wc * 8 + nt) * 2 + 1) * 512 + lane * 16);
        // prefetch afr slot1 <- ks16=3
#pragma unroll
        for (int mt = 0; mt < 4; mt++)
            *(uint4*)afr[1][mt] = *(const uint4*)(sA + ((wr * 4 + mt) * 4 + 3) * 512 + lane * 16);
        // ks16=2
#pragma unroll
        for (int mt = 0; mt < 4; mt++)
#pragma unroll
            for (int nt = 0; nt < 8; nt++)
                mma_f16(acc[mt][nt], afr[0][mt], &bfr[nt][0]);
        cp_commit();                               // one commit per ktile position
        // ks16=3
#pragma unroll
        for (int mt = 0; mt < 4; mt++)
#pragma unroll
            for (int nt = 0; nt < 8; nt++)
                mma_f16(acc[mt][nt], afr[1][mt], &bfr[nt][2]);
    };

    // prologue: stages 0,1
    produceA(0, 0); produceB(0, 0); cp_commit();
    produceA(1, 1); produceB(1, 1); cp_commit();

    // unroll-3 mainloop, round-9-proven ordering: wait -> barrier -> consume(+produce)
#pragma unroll 1
    for (int kt = 0; kt < 30; kt += 3) {
        CP_WAIT(1); __syncthreads();
        consume(0, true, kt + 2, 2);

        CP_WAIT(1); __syncthreads();
        consume(1, true, kt + 3, 0);

        CP_WAIT(1); __syncthreads();
        consume(2, true, kt + 4, 1);
    }
    // tail: kt=30 (stage 0), kt=31 (stage 1); pending g30, g31
    CP_WAIT(1); __syncthreads();
    consume(0, false, 0, 0);
    CP_WAIT(0); __syncthreads();
    consume(1, false, 0, 0);

    // ---- prefetch old_c (coalesced, streaming) while Phase A runs ----
    const int hbase = bn >> 2;
    float ocs[32];
#pragma unroll
    for (int it = 0; it < 32; it++) {
        int idx = it * THREADS + tid;
        int row = idx >> 5;
        int h   = idx & 31;
        ocs[it] = __ldcs(old_c + (size_t)(bm + row) * HDIM + hbase + h);
    }

    __syncthreads();

    // ---- Phase A: dump raw gate pre-activations to smem ----
    // h = wc*16 + nt*2 + (q>>1); even-q lane holds (i,f), odd-q (g,o) of same h
    float* sg = (float*)dsm;
#pragma unroll
    for (int mt = 0; mt < 4; mt++) {
#pragma unroll
        for (int rr = 0; rr < 2; rr++) {
            int row = wr * 64 + mt * 16 + gid + rr * 8;
#pragma unroll
            for (int nt = 0; nt < 8; nt++) {
                int h = wc * 16 + nt * 2 + (q >> 1);
                *(float2*)(sg + (row * 33 + h) * 4 + (q & 1) * 2) =
                    make_float2(acc[mt][nt][rr * 2 + 0], acc[mt][nt][rr * 2 + 1]);
            }
        }
    }
    __syncthreads();

    // ---- Phase B: coalesced cell update + streaming stores ----
    const long long BH = (long long)MDIM * HDIM;
    const bool seg1 = out_size >= 2 * BH;
    const bool seg2 = out_size >= 3 * BH;

#pragma unroll 4
    for (int it = 0; it < 32; it++) {
        int idx = it * THREADS + tid;
        int row = idx >> 5;
        int h   = idx & 31;
        float4 ga = *(const float4*)(sg + (row * 33 + h) * 4);
        float4 bb = s_bias4[h];
        size_t gidx = (size_t)(bm + row) * HDIM + hbase + h;
        float iv = sigmoid_fast(ga.x + bb.x);
        float fv = sigmoid_fast(ga.y + bb.y);
        float gv = tanh_fast(ga.z + bb.z);
        float ov = sigmoid_fast(ga.w + bb.w);
        float nc = fmaf(fv, ocs[it], iv * gv);
        float nh = ov * tanh_fast(nc);
        __stcs(out + gidx, nh);
        if (seg1) __stcs(out + BH + gidx, nh);
        if (seg2) __stcs(out + 2 * BH + gidx, nc);
    }
}

extern "C" void kernel_launch(void* const* d_in, const int* in_sizes, int n_in,
                              void* d_out, int out_size) {
    const float* incoming = (const float*)d_in[0];
    const float* old_h    = (const float*)d_in[1];
    const float* old_c    = (const float*)d_in[2];
    const float* Wi       = (const float*)d_in[3];
    const float* bi       = (const float*)d_in[4];
    const float* Wh       = (const float*)d_in[5];
    float* out = (float*)d_out;

    int aBlocks = (MDIM / 16) * (KDIM / 16) * 32 / 256;   // 16384
    int wBlocks = (NDIM / 8) * (KDIM / 32) * 32 / 256;    // 4096
    pack_AW<<<aBlocks + wBlocks, 256>>>(incoming, old_h, Wi, Wh, aBlocks);

    static int smem_set = 0;
    if (!smem_set) {
        cudaFuncSetAttribute(lstm_mma, cudaFuncAttributeMaxDynamicSharedMemorySize,
                             STAGES * STAGE_BYTES);
        smem_set = 1;
    }
    dim3 grid(NDIM / BN, MDIM / BM);   // (32, 128)
    lstm_mma<<<grid, THREADS, STAGES * STAGE_BYTES>>>(old_c, bi, out, (long long)out_size);
}